// round 1
// baseline (speedup 1.0000x reference)
#include <cuda_runtime.h>

// Problem dims (fixed by the reference)
#define BB   8
#define NSQ  2048
#define DDIM 512
#define MTOT (BB * NSQ)   // 16384 tokens

// Scratch (device globals: allocation-free per harness rules)
__device__ float g_Q[(size_t)MTOT * DDIM];
__device__ float g_K[(size_t)MTOT * DDIM];
__device__ float g_V[(size_t)MTOT * DDIM];
__device__ float g_S[(size_t)BB * NSQ * NSQ];

// ---------------------------------------------------------------------------
// Tiled SGEMM: C[M,N] = A[M,K] * op(B) (+ bias)
//   TRANSB=true : B is [N,K], K-contiguous  (x@W^T, Q@K^T)
//   TRANSB=false: B is [K,N], N-contiguous  (P@V)
// BM=BN=128, BK=16, 256 threads, 8x8 per-thread microtile.
// All dims here are multiples of the tile sizes; no edge guards needed.
// ---------------------------------------------------------------------------
template <bool TRANSB, bool BIAS>
__global__ __launch_bounds__(256, 2)
void sgemm_kernel(const float* __restrict__ A, int lda, long long bsA,
                  const float* __restrict__ B, int ldb, long long bsB,
                  float* __restrict__ C, int ldc, long long bsC,
                  int K, const float* __restrict__ bias)
{
    constexpr int BM = 128, BN = 128, BK = 16, TM = 8, TN = 8;
    __shared__ float As[BK][BM + 4];
    __shared__ float Bs[BK][BN + 4];

    const int tid = threadIdx.x;
    const int tx  = tid & 15;   // 0..15 (N direction)
    const int ty  = tid >> 4;   // 0..15 (M direction)
    const int m0  = blockIdx.y * BM;
    const int n0  = blockIdx.x * BN;

    A += blockIdx.z * bsA + (long long)m0 * lda;
    if (TRANSB) B += blockIdx.z * bsB + (long long)n0 * ldb;
    else        B += blockIdx.z * bsB + n0;
    C += blockIdx.z * bsC + (long long)m0 * ldc + n0;

    float acc[TM][TN];
#pragma unroll
    for (int i = 0; i < TM; i++)
#pragma unroll
        for (int j = 0; j < TN; j++) acc[i][j] = 0.0f;

    for (int k0 = 0; k0 < K; k0 += BK) {
        // --- Load A tile: 128 rows x 16 K, K-contiguous. 256 thr x 2 float4.
#pragma unroll
        for (int l = 0; l < 2; l++) {
            int idx = tid + l * 256;           // 0..511
            int row = idx >> 2;                // 4 float4 per row
            int k4  = (idx & 3) * 4;
            float4 v = *reinterpret_cast<const float4*>(
                A + (long long)row * lda + k0 + k4);
            As[k4 + 0][row] = v.x;
            As[k4 + 1][row] = v.y;
            As[k4 + 2][row] = v.z;
            As[k4 + 3][row] = v.w;
        }
        // --- Load B tile
        if (TRANSB) {
#pragma unroll
            for (int l = 0; l < 2; l++) {
                int idx = tid + l * 256;
                int row = idx >> 2;            // N index within tile
                int k4  = (idx & 3) * 4;
                float4 v = *reinterpret_cast<const float4*>(
                    B + (long long)row * ldb + k0 + k4);
                Bs[k4 + 0][row] = v.x;
                Bs[k4 + 1][row] = v.y;
                Bs[k4 + 2][row] = v.z;
                Bs[k4 + 3][row] = v.w;
            }
        } else {
#pragma unroll
            for (int l = 0; l < 2; l++) {
                int idx = tid + l * 256;       // 32 float4 per K-row
                int row = idx >> 5;            // K index within tile
                int n4  = (idx & 31) * 4;
                float4 v = *reinterpret_cast<const float4*>(
                    B + (long long)(k0 + row) * ldb + n4);
                Bs[row][n4 + 0] = v.x;
                Bs[row][n4 + 1] = v.y;
                Bs[row][n4 + 2] = v.z;
                Bs[row][n4 + 3] = v.w;
            }
        }
        __syncthreads();

#pragma unroll
        for (int kk = 0; kk < BK; kk++) {
            float a[TM], b[TN];
#pragma unroll
            for (int i = 0; i < TM; i++) a[i] = As[kk][ty * TM + i];
#pragma unroll
            for (int j = 0; j < TN; j++) b[j] = Bs[kk][tx * TN + j];
#pragma unroll
            for (int i = 0; i < TM; i++)
#pragma unroll
                for (int j = 0; j < TN; j++)
                    acc[i][j] += a[i] * b[j];
        }
        __syncthreads();
    }

#pragma unroll
    for (int i = 0; i < TM; i++) {
#pragma unroll
        for (int j = 0; j < TN; j++) {
            float v = acc[i][j];
            if (BIAS) v += bias[n0 + tx * TN + j];
            C[(long long)(ty * TM + i) * ldc + tx * TN + j] = v;
        }
    }
}

// ---------------------------------------------------------------------------
// Row softmax over length-2048 rows, in place. One block (256 thr) per row,
// 8 elements per thread held in registers. Max-subtraction is required:
// unscaled logits reach ~±90 (exp would overflow fp32).
// ---------------------------------------------------------------------------
__global__ __launch_bounds__(256)
void softmax_kernel(float* __restrict__ S)
{
    const long long row = blockIdx.x;
    float* p = S + row * (long long)NSQ;
    const int tid = threadIdx.x;

    float vals[8];
    float m = -3.0e38f;
#pragma unroll
    for (int i = 0; i < 8; i++) {
        vals[i] = p[tid + i * 256];
        m = fmaxf(m, vals[i]);
    }

    __shared__ float red[256];
    red[tid] = m;
    __syncthreads();
#pragma unroll
    for (int s = 128; s > 0; s >>= 1) {
        if (tid < s) red[tid] = fmaxf(red[tid], red[tid + s]);
        __syncthreads();
    }
    m = red[0];
    __syncthreads();

    float sum = 0.0f;
#pragma unroll
    for (int i = 0; i < 8; i++) {
        vals[i] = __expf(vals[i] - m);
        sum += vals[i];
    }
    red[tid] = sum;
    __syncthreads();
#pragma unroll
    for (int s = 128; s > 0; s >>= 1) {
        if (tid < s) red[tid] += red[tid + s];
        __syncthreads();
    }
    const float inv = 1.0f / red[0];
#pragma unroll
    for (int i = 0; i < 8; i++) p[tid + i * 256] = vals[i] * inv;
}

// ---------------------------------------------------------------------------
// Launch: QKV projections (3 SGEMMs) -> scores (batched) -> softmax -> PV
// ---------------------------------------------------------------------------
extern "C" void kernel_launch(void* const* d_in, const int* in_sizes, int n_in,
                              void* d_out, int out_size)
{
    const float* x  = (const float*)d_in[0];
    const float* Wq = (const float*)d_in[1];
    const float* bq = (const float*)d_in[2];
    const float* Wk = (const float*)d_in[3];
    const float* bk = (const float*)d_in[4];
    const float* Wv = (const float*)d_in[5];
    const float* bv = (const float*)d_in[6];
    float* out = (float*)d_out;

    float *Q, *K, *V, *S;
    cudaGetSymbolAddress((void**)&Q, g_Q);
    cudaGetSymbolAddress((void**)&K, g_K);
    cudaGetSymbolAddress((void**)&V, g_V);
    cudaGetSymbolAddress((void**)&S, g_S);

    // 1) QKV projections: [16384,512] x [512,512]^T + bias
    {
        dim3 grid(DDIM / 128, MTOT / 128, 1);
        sgemm_kernel<true, true><<<grid, 256>>>(
            x, DDIM, 0, Wq, DDIM, 0, Q, DDIM, 0, DDIM, bq);
        sgemm_kernel<true, true><<<grid, 256>>>(
            x, DDIM, 0, Wk, DDIM, 0, K, DDIM, 0, DDIM, bk);
        sgemm_kernel<true, true><<<grid, 256>>>(
            x, DDIM, 0, Wv, DDIM, 0, V, DDIM, 0, DDIM, bv);
    }

    // 2) Scores: per batch  S_b[2048,2048] = Q_b @ K_b^T
    {
        dim3 grid(NSQ / 128, NSQ / 128, BB);
        sgemm_kernel<true, false><<<grid, 256>>>(
            Q, DDIM, (long long)NSQ * DDIM,
            K, DDIM, (long long)NSQ * DDIM,
            S, NSQ,  (long long)NSQ * NSQ,
            DDIM, nullptr);
    }

    // 3) Row softmax (in place), 16384 rows
    softmax_kernel<<<BB * NSQ, 256>>>(S);

    // 4) Output: per batch  O_b[2048,512] = P_b @ V_b
    {
        dim3 grid(DDIM / 128, NSQ / 128, BB);
        sgemm_kernel<false, false><<<grid, 256>>>(
            S, NSQ,  (long long)NSQ * NSQ,
            V, DDIM, (long long)NSQ * DDIM,
            out, DDIM, (long long)NSQ * DDIM,
            NSQ, nullptr);
    }
}

// round 6
// speedup vs baseline: 2.3594x; 2.3594x over previous
#include <cuda_runtime.h>
#include <cstdint>

#define BB   8
#define NSQ  2048
#define DDIM 512
#define MTOT (BB * NSQ)

__device__ float g_Q[(size_t)MTOT * DDIM];
__device__ float g_K[(size_t)MTOT * DDIM];
__device__ float g_V[(size_t)MTOT * DDIM];
__device__ float g_S[(size_t)BB * NSQ * NSQ];

// ---------------------------------------------------------------------------
// helpers
// ---------------------------------------------------------------------------
static __device__ __forceinline__ uint32_t smem_u32(const void* p) {
    uint32_t a;
    asm("{ .reg .u64 t; cvta.to.shared.u64 t, %1; cvt.u32.u64 %0, t; }"
        : "=r"(a) : "l"(p));
    return a;
}
static __device__ __forceinline__ void cpa16(uint32_t dst, const void* src) {
    asm volatile("cp.async.cg.shared.global [%0], [%1], 16;"
                 :: "r"(dst), "l"(src) : "memory");
}
#define CP_COMMIT() asm volatile("cp.async.commit_group;" ::: "memory")
#define CP_WAIT1()  asm volatile("cp.async.wait_group 1;" ::: "memory")
#define CP_WAIT0()  asm volatile("cp.async.wait_group 0;" ::: "memory")

// Split two fp32 (x = element k, y = element k+1) into packed bf16x2 hi/lo.
// hi = bitwise truncation (exact top 16 bits), lo = rn(residual).
static __device__ __forceinline__ void split2(float x, float y,
                                              uint32_t& hi2, uint32_t& lo2) {
    uint32_t xb = __float_as_uint(x), yb = __float_as_uint(y);
    uint32_t h;
    asm("prmt.b32 %0, %1, %2, 0x7632;" : "=r"(h) : "r"(xb), "r"(yb));
    float xl = x - __uint_as_float(xb & 0xFFFF0000u);
    float yl = y - __uint_as_float(yb & 0xFFFF0000u);
    uint32_t l;
    asm("cvt.rn.bf16x2.f32 %0, %1, %2;" : "=r"(l) : "f"(yl), "f"(xl));
    hi2 = h; lo2 = l;
}

static __device__ __forceinline__ void mma16816(float c[4],
                                                uint32_t a0, uint32_t a1,
                                                uint32_t a2, uint32_t a3,
                                                uint32_t b0, uint32_t b1) {
    asm volatile(
        "mma.sync.aligned.m16n8k16.row.col.f32.bf16.bf16.f32 "
        "{%0,%1,%2,%3}, {%4,%5,%6,%7}, {%8,%9}, {%0,%1,%2,%3};"
        : "+f"(c[0]), "+f"(c[1]), "+f"(c[2]), "+f"(c[3])
        : "r"(a0), "r"(a1), "r"(a2), "r"(a3), "r"(b0), "r"(b1));
}

// ---------------------------------------------------------------------------
// 3xBF16 GEMM: C[128,128] per block = A[128,K] @ op(B) (+bias), fp32 in/out.
//   BT=true : B is [N,K], K-contiguous (x@W^T, Q@K^T)
//   BT=false: B is [K,N], N-contiguous (P@V)
// 256 threads = 8 warps (2m x 4n), warp tile 64x32, mma m16n8k16.
// 3-stage cp.async pipeline, BK=32.
// smem strides: A/B(BT) rows padded to 40 floats; B(!BT) rows 140 floats.
// ---------------------------------------------------------------------------
#define SA 40
#define SBN 140
#define A_TILE_F (128 * SA)            // 5120 floats
#define BT_TILE_F (128 * SA)
#define BN_TILE_F (32 * SBN)           // 4480 floats
#define STAGE_F_BT (A_TILE_F + BT_TILE_F)
#define STAGE_F_BN (A_TILE_F + BN_TILE_F)

template <bool BT, bool BIAS>
__global__ __launch_bounds__(256, 1)
void mm_bf16x3(const float* __restrict__ A, int lda, long long bsA,
               const float* __restrict__ B, int ldb, long long bsB,
               float* __restrict__ C, int ldc, long long bsC,
               int K, const float* __restrict__ bias)
{
    extern __shared__ float smf[];
    const int tid  = threadIdx.x;
    const int lane = tid & 31, w = tid >> 5;
    const int wm = w & 1, wn = w >> 1;     // 2 x 4 warp grid
    const int g = lane >> 2, t = lane & 3;
    const int m0 = blockIdx.y * 128;
    const int n0 = blockIdx.x * 128;

    A += blockIdx.z * bsA + (long long)m0 * lda;
    if (BT) B += blockIdx.z * bsB + (long long)n0 * ldb;
    else    B += blockIdx.z * bsB + n0;
    C += blockIdx.z * bsC + (long long)m0 * ldc + n0;

    const int STAGE_F = BT ? STAGE_F_BT : STAGE_F_BN;
    const uint32_t sbase = smem_u32(smf);
    const int KT = K / 32;

    float acc[4][4][4];
#pragma unroll
    for (int mi = 0; mi < 4; mi++)
#pragma unroll
        for (int ni = 0; ni < 4; ni++)
#pragma unroll
            for (int r = 0; r < 4; r++) acc[mi][ni][r] = 0.0f;

    // ---- async tile loader ------------------------------------------------
    auto load_tile = [&](int stage, int kt) {
        const int kofs = kt * 32;
        const uint32_t st = sbase + stage * STAGE_F * 4;
        // A: 128 rows x 32 floats, 8 x 16B chunks per row
#pragma unroll
        for (int j = 0; j < 4; j++) {
            int idx = tid + j * 256;
            int row = idx >> 3, k4 = idx & 7;
            cpa16(st + row * (SA * 4) + k4 * 16,
                  A + (long long)row * lda + kofs + k4 * 4);
        }
        const uint32_t bt = st + A_TILE_F * 4;
        if (BT) {
#pragma unroll
            for (int j = 0; j < 4; j++) {
                int idx = tid + j * 256;
                int row = idx >> 3, k4 = idx & 7;
                cpa16(bt + row * (SA * 4) + k4 * 16,
                      B + (long long)row * ldb + kofs + k4 * 4);
            }
        } else {
            // B tile: 32 k-rows x 128 floats, 32 chunks per row
#pragma unroll
            for (int j = 0; j < 4; j++) {
                int idx = tid + j * 256;
                int kk = idx >> 5, n4 = idx & 31;
                cpa16(bt + kk * (SBN * 4) + n4 * 16,
                      B + (long long)(kofs + kk) * ldb + n4 * 4);
            }
        }
    };

    // ---- compute one ktile ------------------------------------------------
    auto compute = [&](int stage) {
        const float* As = smf + stage * STAGE_F;
        const float* Bs = As + A_TILE_F;
#pragma unroll
        for (int ks = 0; ks < 2; ks++) {
            const int kb = ks * 16;
            uint32_t Ah[4][4], Al[4][4], Bh[4][2], Bl[4][2];
#pragma unroll
            for (int mi = 0; mi < 4; mi++) {
#pragma unroll
                for (int q = 0; q < 2; q++)
#pragma unroll
                    for (int h = 0; h < 2; h++) {
                        const float2 v = *reinterpret_cast<const float2*>(
                            As + (wm * 64 + mi * 16 + g + 8 * h) * SA
                               + kb + 2 * t + 8 * q);
                        split2(v.x, v.y, Ah[mi][h + 2 * q], Al[mi][h + 2 * q]);
                    }
            }
#pragma unroll
            for (int ni = 0; ni < 4; ni++) {
                const int n = wn * 32 + ni * 8 + g;
#pragma unroll
                for (int h = 0; h < 2; h++) {
                    float x, y;
                    if (BT) {
                        const float2 v = *reinterpret_cast<const float2*>(
                            Bs + n * SA + kb + 2 * t + 8 * h);
                        x = v.x; y = v.y;
                    } else {
                        x = Bs[(kb + 2 * t + 8 * h) * SBN + n];
                        y = Bs[(kb + 2 * t + 1 + 8 * h) * SBN + n];
                    }
                    split2(x, y, Bh[ni][h], Bl[ni][h]);
                }
            }
#pragma unroll
            for (int mi = 0; mi < 4; mi++)
#pragma unroll
                for (int ni = 0; ni < 4; ni++) {
                    float* c = acc[mi][ni];
                    mma16816(c, Ah[mi][0], Ah[mi][1], Ah[mi][2], Ah[mi][3],
                             Bh[ni][0], Bh[ni][1]);
                    mma16816(c, Ah[mi][0], Ah[mi][1], Ah[mi][2], Ah[mi][3],
                             Bl[ni][0], Bl[ni][1]);
                    mma16816(c, Al[mi][0], Al[mi][1], Al[mi][2], Al[mi][3],
                             Bh[ni][0], Bh[ni][1]);
                }
        }
    };

    // ---- pipeline ---------------------------------------------------------
    load_tile(0, 0); CP_COMMIT();
    load_tile(1, 1); CP_COMMIT();

#pragma unroll 1
    for (int kt = 0; kt < KT; kt++) {
        if (kt < KT - 1) { CP_WAIT1(); } else { CP_WAIT0(); }
        __syncthreads();
        if (kt + 2 < KT) { load_tile((kt + 2) % 3, kt + 2); CP_COMMIT(); }
        compute(kt % 3);
    }

    // ---- epilogue ---------------------------------------------------------
#pragma unroll
    for (int mi = 0; mi < 4; mi++) {
#pragma unroll
        for (int ni = 0; ni < 4; ni++) {
            const int col = wn * 32 + ni * 8 + 2 * t;
            float bx = 0.0f, by = 0.0f;
            if (BIAS) {
                const float2 bv = *reinterpret_cast<const float2*>(bias + n0 + col);
                bx = bv.x; by = bv.y;
            }
            const int r0 = wm * 64 + mi * 16 + g;
            float2 o0, o1;
            o0.x = acc[mi][ni][0] + bx; o0.y = acc[mi][ni][1] + by;
            o1.x = acc[mi][ni][2] + bx; o1.y = acc[mi][ni][3] + by;
            *reinterpret_cast<float2*>(C + (long long)r0 * ldc + col) = o0;
            *reinterpret_cast<float2*>(C + (long long)(r0 + 8) * ldc + col) = o1;
        }
    }
}

// ---------------------------------------------------------------------------
// Row softmax over length-2048 rows, in place. Max-subtraction mandatory
// (unscaled logits reach ~±90).
// ---------------------------------------------------------------------------
__global__ __launch_bounds__(256)
void softmax_kernel(float* __restrict__ S)
{
    const long long row = blockIdx.x;
    float* p = S + row * (long long)NSQ;
    const int tid = threadIdx.x;

    float vals[8];
    float m = -3.0e38f;
#pragma unroll
    for (int i = 0; i < 8; i++) {
        vals[i] = p[tid + i * 256];
        m = fmaxf(m, vals[i]);
    }
    __shared__ float red[256];
    red[tid] = m;
    __syncthreads();
#pragma unroll
    for (int s = 128; s > 0; s >>= 1) {
        if (tid < s) red[tid] = fmaxf(red[tid], red[tid + s]);
        __syncthreads();
    }
    m = red[0];
    __syncthreads();

    float sum = 0.0f;
#pragma unroll
    for (int i = 0; i < 8; i++) {
        vals[i] = __expf(vals[i] - m);
        sum += vals[i];
    }
    red[tid] = sum;
    __syncthreads();
#pragma unroll
    for (int s = 128; s > 0; s >>= 1) {
        if (tid < s) red[tid] += red[tid + s];
        __syncthreads();
    }
    const float inv = 1.0f / red[0];
#pragma unroll
    for (int i = 0; i < 8; i++) p[tid + i * 256] = vals[i] * inv;
}

// ---------------------------------------------------------------------------
// Launch
// ---------------------------------------------------------------------------
extern "C" void kernel_launch(void* const* d_in, const int* in_sizes, int n_in,
                              void* d_out, int out_size)
{
    const float* x  = (const float*)d_in[0];
    const float* Wq = (const float*)d_in[1];
    const float* bq = (const float*)d_in[2];
    const float* Wk = (const float*)d_in[3];
    const float* bk = (const float*)d_in[4];
    const float* Wv = (const float*)d_in[5];
    const float* bv = (const float*)d_in[6];
    float* out = (float*)d_out;

    float *Q, *K, *V, *S;
    cudaGetSymbolAddress((void**)&Q, g_Q);
    cudaGetSymbolAddress((void**)&K, g_K);
    cudaGetSymbolAddress((void**)&V, g_V);
    cudaGetSymbolAddress((void**)&S, g_S);

    const int SMEM_BT = 3 * STAGE_F_BT * 4;   // 122880 B
    const int SMEM_BN = 3 * STAGE_F_BN * 4;   // 115200 B

    cudaFuncSetAttribute(mm_bf16x3<true, true>,
                         cudaFuncAttributeMaxDynamicSharedMemorySize, SMEM_BT);
    cudaFuncSetAttribute(mm_bf16x3<true, false>,
                         cudaFuncAttributeMaxDynamicSharedMemorySize, SMEM_BT);
    cudaFuncSetAttribute(mm_bf16x3<false, false>,
                         cudaFuncAttributeMaxDynamicSharedMemorySize, SMEM_BN);

    // 1) Projections: [16384,512] = x @ W^T + b
    {
        dim3 grid(DDIM / 128, MTOT / 128, 1);
        mm_bf16x3<true, true><<<grid, 256, SMEM_BT>>>(
            x, DDIM, 0, Wq, DDIM, 0, Q, DDIM, 0, DDIM, bq);
        mm_bf16x3<true, true><<<grid, 256, SMEM_BT>>>(
            x, DDIM, 0, Wk, DDIM, 0, K, DDIM, 0, DDIM, bk);
        mm_bf16x3<true, true><<<grid, 256, SMEM_BT>>>(
            x, DDIM, 0, Wv, DDIM, 0, V, DDIM, 0, DDIM, bv);
    }
    // 2) Scores: S_b = Q_b @ K_b^T
    {
        dim3 grid(NSQ / 128, NSQ / 128, BB);
        mm_bf16x3<true, false><<<grid, 256, SMEM_BT>>>(
            Q, DDIM, (long long)NSQ * DDIM,
            K, DDIM, (long long)NSQ * DDIM,
            S, NSQ,  (long long)NSQ * NSQ,
            DDIM, nullptr);
    }
    // 3) Softmax rows
    softmax_kernel<<<BB * NSQ, 256>>>(S);
    // 4) Output: O_b = P_b @ V_b
    {
        dim3 grid(DDIM / 128, NSQ / 128, BB);
        mm_bf16x3<false, false><<<grid, 256, SMEM_BN>>>(
            S, NSQ,  (long long)NSQ * NSQ,
            V, DDIM, (long long)NSQ * DDIM,
            out, DDIM, (long long)NSQ * DDIM,
            NSQ, nullptr);
    }
}